// round 13
// baseline (speedup 1.0000x reference)
#include <cuda_runtime.h>
#include <cuda_bf16.h>

// Problem constants
#define NB    4
#define NC    2000      // curves per batch
#define NLS   2000      // line samples per batch
#define NS    4000      // surfaces per batch
#define NF    8000      // faces per batch
#define NTS   26000     // triangle samples per batch
#define NPT   (NC + NLS + NS + NTS)   // 34000 points per batch
#define NPTOT (NB * NPT)              // 136000 points total
#define OG    258       // occ grid edge (256 + 2*2 pad - 3 + 1)
#define OGSQ  (OG * OG)                        // 66564
#define X_ELEMS   (NB * NPT * 3)               // 408000
#define OCC_PER_B 17173512L                    // OG^3, divisible by 8
#define OCC_ELEMS (NB * OCC_PER_B)             // 68,669,448

// Bitmap: 1 bit per voxel, per batch.
#define WPB   536673                           // ceil(OCC_PER_B / 32)
#define NW    (NB * WPB)
#define Q_PER_B ((int)(OCC_PER_B / 4))         // 4,293,378 float4 per batch

// Bitmap scratch. Zero-initialized at module load; the sweep kernel re-zeros
// every word it consumes, so the invariant "bitmap is all-zero at
// kernel_launch entry" holds on the first call AND on every graph replay.
__device__ uint4 g_bitmap4[(NW + 3) / 4];

// ---------------------------------------------------------------------------
// Kernel 1: one thread per point. Computes the point with the exact f32 op
// order of the reference (no FMA contraction), writes x, and sets the 27
// dilated occupancy bits (9 rows of 3 consecutive bits) via atomicOr.
// Dilation == padded 3-maxpool of the one-hot grid; coords always in-bounds
// (c in [0,255] -> voxel coords in [0,257]).
// ---------------------------------------------------------------------------
__device__ __forceinline__ int cube_coord(float p) {
    float t = __fadd_rn(__fmul_rn(p, 256.0f), 128.5f);
    t = fminf(255.0f, fmaxf(0.0f, t));
    return (int)t;   // t >= 0 so truncation == floor
}

__global__ void points_kernel(const float* __restrict__ curves,
                              const float* __restrict__ surfaces,
                              const float* __restrict__ t_line,
                              const float* __restrict__ uv,
                              const int*   __restrict__ lines_array,
                              const int*   __restrict__ faces_array,
                              const int*   __restrict__ line_choice,
                              const int*   __restrict__ tri_choice,
                              float* __restrict__ out) {
    int idx = blockIdx.x * blockDim.x + threadIdx.x;
    if (idx >= NPTOT) return;
    int b = idx / NPT;
    int j = idx - b * NPT;

    float p0, p1, p2;

    if (j < NC) {
        // segment 0: curves passthrough
        const float* c = curves + ((long)(b * NC + j)) * 3;
        p0 = c[0]; p1 = c[1]; p2 = c[2];
    } else if (j < NC + NLS) {
        // segment 1: line interpolation  a + t*(b-a)
        int jj = j - NC;
        int lc = line_choice[b * NLS + jj];
        int s0 = lines_array[((long)(b * NC + lc)) * 2 + 0];
        int s1 = lines_array[((long)(b * NC + lc)) * 2 + 1];
        const float* A  = curves + ((long)(b * NC + s0)) * 3;
        const float* Bp = curves + ((long)(b * NC + s1)) * 3;
        float t = t_line[b * NLS + jj];
        p0 = __fadd_rn(A[0], __fmul_rn(t, __fsub_rn(Bp[0], A[0])));
        p1 = __fadd_rn(A[1], __fmul_rn(t, __fsub_rn(Bp[1], A[1])));
        p2 = __fadd_rn(A[2], __fmul_rn(t, __fsub_rn(Bp[2], A[2])));
    } else if (j < NC + NLS + NS) {
        // segment 2: surfaces passthrough
        int jj = j - (NC + NLS);
        const float* s = surfaces + ((long)(b * NS + jj)) * 3;
        p0 = s[0]; p1 = s[1]; p2 = s[2];
    } else {
        // segment 3: triangle barycentric sample
        int jj = j - (NC + NLS + NS);
        int tc = tri_choice[b * NTS + jj];
        const int* f = faces_array + ((long)(b * NF + tc)) * 3;
        const float* ta  = surfaces + ((long)(b * NS + f[0])) * 3;
        const float* tb  = surfaces + ((long)(b * NS + f[1])) * 3;
        const float* tcx = surfaces + ((long)(b * NS + f[2])) * 3;
        float u = uv[((long)(b * NTS + jj)) * 2 + 0];
        float v = uv[((long)(b * NTS + jj)) * 2 + 1];
        if (__fadd_rn(u, v) > 1.0f) {
            u = __fsub_rn(1.0f, u);
            v = __fsub_rn(1.0f, v);
        }
        // (ta + u*(tb-ta)) + v*(tc-ta), exact reference op order
        p0 = __fadd_rn(__fadd_rn(ta[0], __fmul_rn(u, __fsub_rn(tb[0], ta[0]))),
                       __fmul_rn(v, __fsub_rn(tcx[0], ta[0])));
        p1 = __fadd_rn(__fadd_rn(ta[1], __fmul_rn(u, __fsub_rn(tb[1], ta[1]))),
                       __fmul_rn(v, __fsub_rn(tcx[1], ta[1])));
        p2 = __fadd_rn(__fadd_rn(ta[2], __fmul_rn(u, __fsub_rn(tb[2], ta[2]))),
                       __fmul_rn(v, __fsub_rn(tcx[2], ta[2])));
    }

    // write x
    float* xo = out + ((long)idx) * 3;
    xo[0] = p0; xo[1] = p1; xo[2] = p2;

    // set 27 dilated bits: 9 rows of 3 consecutive bits
    int c0 = cube_coord(p0);
    int c1 = cube_coord(p1);
    int c2 = cube_coord(p2);
    unsigned int* bm = (unsigned int*)g_bitmap4 + b * WPB;
    #pragma unroll
    for (int d0 = 0; d0 < 3; d0++) {
        long base0 = (long)(c0 + d0) * OGSQ;
        #pragma unroll
        for (int d1 = 0; d1 < 3; d1++) {
            long p = base0 + (long)(c1 + d1) * OG + c2;   // first of 3 bits
            int w = (int)(p >> 5);
            int s = (int)(p & 31);
            atomicOr(&bm[w], 7u << s);                    // in-word part
            if (s > 29)                                   // spill into next word
                atomicOr(&bm[w + 1], 7u >> (32 - s));
        }
    }
}

// ---------------------------------------------------------------------------
// Kernel 2: dense sweep, one thread per float4 (lane-contiguous -> perfectly
// coalesced 16B stores; 8 adjacent lanes broadcast-load one bitmap word).
// After all lanes in the warp have loaded (__syncwarp), the owner lane of
// each word resets it to 0, restoring the all-zero bitmap invariant for the
// next graph replay. 274 MB written exactly once, dense, nothing co-resident.
// ---------------------------------------------------------------------------
__global__ void sweep_kernel(float* __restrict__ out) {
    int q = blockIdx.x * blockDim.x + threadIdx.x;   // float4 index in batch
    int b = blockIdx.y;
    bool valid = (q < Q_PER_B);

    unsigned int* bm = (unsigned int*)g_bitmap4 + b * WPB;
    long v = (long)q * 4;                 // first voxel of this float4
    int  w = (int)(v >> 5);
    int  s = (int)(v & 31);

    unsigned int bits = 0;
    if (valid) bits = bm[w];              // 1 load per 8 lanes (broadcast)
    __syncwarp(0xFFFFFFFFu);              // all loads done before re-zero
    if (valid && s == 0) bm[w] = 0;       // owner lane resets the word

    if (valid) {
        float4 f;
        f.x = (bits >> (s + 0)) & 1u ? 1.0f : 0.0f;
        f.y = (bits >> (s + 1)) & 1u ? 1.0f : 0.0f;
        f.z = (bits >> (s + 2)) & 1u ? 1.0f : 0.0f;
        f.w = (bits >> (s + 3)) & 1u ? 1.0f : 0.0f;
        float* occ = out + X_ELEMS + (long)b * OCC_PER_B;
        *(float4*)(occ + v) = f;
    }
}

extern "C" void kernel_launch(void* const* d_in, const int* in_sizes, int n_in,
                              void* d_out, int out_size) {
    // metadata order:
    // 0 imgs (unused), 1 curves, 2 surfaces, 3 t_line, 4 uv,
    // 5 lines_array, 6 faces_array, 7 indices_array (unused),
    // 8 line_choice, 9 tri_choice
    const float* curves      = (const float*)d_in[1];
    const float* surfaces    = (const float*)d_in[2];
    const float* t_line      = (const float*)d_in[3];
    const float* uv          = (const float*)d_in[4];
    const int*   lines_array = (const int*)d_in[5];
    const int*   faces_array = (const int*)d_in[6];
    const int*   line_choice = (const int*)d_in[8];
    const int*   tri_choice  = (const int*)d_in[9];
    float* out = (float*)d_out;

    // k0: points + bit scatter (bitmap is all-zero at entry: zero-init on
    // first call, re-zeroed by the previous sweep on every replay)
    int pb = (NPTOT + 255) / 256;
    points_kernel<<<pb, 256>>>(curves, surfaces, t_line, uv,
                               lines_array, faces_array,
                               line_choice, tri_choice, out);

    // k1: dense 274 MB sweep from bitmap (+ bitmap self-reset)
    dim3 sg((Q_PER_B + 255) / 256, NB, 1);   // (16772, 4)
    sweep_kernel<<<sg, 256>>>(out);
}

// round 14
// speedup vs baseline: 1.3339x; 1.3339x over previous
#include <cuda_runtime.h>
#include <cuda_bf16.h>

// Problem constants
#define NB    4
#define NC    2000      // curves per batch
#define NLS   2000      // line samples per batch
#define NS    4000      // surfaces per batch
#define NF    8000      // faces per batch
#define NTS   26000     // triangle samples per batch
#define NPT   (NC + NLS + NS + NTS)   // 34000 points per batch
#define NPTOT (NB * NPT)              // 136000 points total
#define OG    258       // occ grid edge (256 + 2*2 pad - 3 + 1)
#define OGSQ  (OG * OG)                        // 66564
#define X_ELEMS   (NB * NPT * 3)               // 408000
#define OCC_PER_B 17173512L                    // OG^3, divisible by 8
#define OCC_ELEMS (NB * OCC_PER_B)             // 68,669,448

// Bitmap: 1 bit per voxel, per batch.
#define WPB   536673                           // ceil(OCC_PER_B / 32)
#define NW    (NB * WPB)
#define Q_PER_B ((int)(OCC_PER_B / 4))         // 4,293,378 float4 per batch
#define CPB   16772                            // chunks (1024 voxels) per batch
#define NCH   (NB * CPB)                       // 67088 chunks total

// Bitmap scratch. Zero-initialized at module load; the sweep kernel re-zeros
// every word it consumes, so "bitmap all-zero at kernel_launch entry" holds
// on the first call AND on every graph replay.
__device__ uint4 g_bitmap4[(NW + 3) / 4];

// ---------------------------------------------------------------------------
// Kernel 1: one thread per point. Computes the point with the exact f32 op
// order of the reference (no FMA contraction), writes x, and sets the 27
// dilated occupancy bits (9 rows of 3 consecutive bits) via atomicOr.
// Dilation == padded 3-maxpool of the one-hot grid; coords always in-bounds
// (c in [0,255] -> voxel coords in [0,257]).
// ---------------------------------------------------------------------------
__device__ __forceinline__ int cube_coord(float p) {
    float t = __fadd_rn(__fmul_rn(p, 256.0f), 128.5f);
    t = fminf(255.0f, fmaxf(0.0f, t));
    return (int)t;   // t >= 0 so truncation == floor
}

__global__ void points_kernel(const float* __restrict__ curves,
                              const float* __restrict__ surfaces,
                              const float* __restrict__ t_line,
                              const float* __restrict__ uv,
                              const int*   __restrict__ lines_array,
                              const int*   __restrict__ faces_array,
                              const int*   __restrict__ line_choice,
                              const int*   __restrict__ tri_choice,
                              float* __restrict__ out) {
    int idx = blockIdx.x * blockDim.x + threadIdx.x;
    if (idx >= NPTOT) return;
    int b = idx / NPT;
    int j = idx - b * NPT;

    float p0, p1, p2;

    if (j < NC) {
        // segment 0: curves passthrough
        const float* c = curves + ((long)(b * NC + j)) * 3;
        p0 = c[0]; p1 = c[1]; p2 = c[2];
    } else if (j < NC + NLS) {
        // segment 1: line interpolation  a + t*(b-a)
        int jj = j - NC;
        int lc = line_choice[b * NLS + jj];
        int s0 = lines_array[((long)(b * NC + lc)) * 2 + 0];
        int s1 = lines_array[((long)(b * NC + lc)) * 2 + 1];
        const float* A  = curves + ((long)(b * NC + s0)) * 3;
        const float* Bp = curves + ((long)(b * NC + s1)) * 3;
        float t = t_line[b * NLS + jj];
        p0 = __fadd_rn(A[0], __fmul_rn(t, __fsub_rn(Bp[0], A[0])));
        p1 = __fadd_rn(A[1], __fmul_rn(t, __fsub_rn(Bp[1], A[1])));
        p2 = __fadd_rn(A[2], __fmul_rn(t, __fsub_rn(Bp[2], A[2])));
    } else if (j < NC + NLS + NS) {
        // segment 2: surfaces passthrough
        int jj = j - (NC + NLS);
        const float* s = surfaces + ((long)(b * NS + jj)) * 3;
        p0 = s[0]; p1 = s[1]; p2 = s[2];
    } else {
        // segment 3: triangle barycentric sample
        int jj = j - (NC + NLS + NS);
        int tc = tri_choice[b * NTS + jj];
        const int* f = faces_array + ((long)(b * NF + tc)) * 3;
        const float* ta  = surfaces + ((long)(b * NS + f[0])) * 3;
        const float* tb  = surfaces + ((long)(b * NS + f[1])) * 3;
        const float* tcx = surfaces + ((long)(b * NS + f[2])) * 3;
        float u = uv[((long)(b * NTS + jj)) * 2 + 0];
        float v = uv[((long)(b * NTS + jj)) * 2 + 1];
        if (__fadd_rn(u, v) > 1.0f) {
            u = __fsub_rn(1.0f, u);
            v = __fsub_rn(1.0f, v);
        }
        // (ta + u*(tb-ta)) + v*(tc-ta), exact reference op order
        p0 = __fadd_rn(__fadd_rn(ta[0], __fmul_rn(u, __fsub_rn(tb[0], ta[0]))),
                       __fmul_rn(v, __fsub_rn(tcx[0], ta[0])));
        p1 = __fadd_rn(__fadd_rn(ta[1], __fmul_rn(u, __fsub_rn(tb[1], ta[1]))),
                       __fmul_rn(v, __fsub_rn(tcx[1], ta[1])));
        p2 = __fadd_rn(__fadd_rn(ta[2], __fmul_rn(u, __fsub_rn(tb[2], ta[2]))),
                       __fmul_rn(v, __fsub_rn(tcx[2], ta[2])));
    }

    // write x
    float* xo = out + ((long)idx) * 3;
    xo[0] = p0; xo[1] = p1; xo[2] = p2;

    // set 27 dilated bits: 9 rows of 3 consecutive bits
    int c0 = cube_coord(p0);
    int c1 = cube_coord(p1);
    int c2 = cube_coord(p2);
    unsigned int* bm = (unsigned int*)g_bitmap4 + b * WPB;
    #pragma unroll
    for (int d0 = 0; d0 < 3; d0++) {
        long base0 = (long)(c0 + d0) * OGSQ;
        #pragma unroll
        for (int d1 = 0; d1 < 3; d1++) {
            long p = base0 + (long)(c1 + d1) * OG + c2;   // first of 3 bits
            int w = (int)(p >> 5);
            int s = (int)(p & 31);
            atomicOr(&bm[w], 7u << s);                    // in-word part
            if (s > 29)                                   // spill into next word
                atomicOr(&bm[w + 1], 7u >> (32 - s));
        }
    }
}

// ---------------------------------------------------------------------------
// Kernel 2: warp-centric dense sweep. Each warp owns one chunk of 1024
// consecutive voxels = 32 bitmap words = one 128B bitmap line:
//   - lane l loads word c*32+l (ONE coalesced LDG.32 per warp, 128B read
//     per 4KB written) and re-zeros it (coalesced full-line store ->
//     preserves the all-zero invariant for the next replay, no races:
//     each word is touched by exactly its owning warp).
//   - 8 store iterations: at iter i, lane l stores float4 c*256+i*32+l
//     (lane-contiguous -> perfect 512B/warp STG.128 wavefronts). The nibble
//     it needs lives in lane i*4+(l>>3) at bit offset (l&7)*4, fetched via
//     one __shfl_sync per iteration. No barriers, no divergence (guards are
//     predicated; shfl is executed by all lanes).
// 1D grid over all chunks -> linear block->address mapping, same dense
// ordering as the proven-6.4TB/s zero kernels.
// ---------------------------------------------------------------------------
__global__ void sweep_kernel(float* __restrict__ out) {
    int warp_g = (blockIdx.x * blockDim.x + threadIdx.x) >> 5;  // chunk id
    int lane   = threadIdx.x & 31;
    if (warp_g >= NCH) return;

    int b = warp_g / CPB;
    int c = warp_g - b * CPB;             // chunk within batch

    unsigned int* bm = (unsigned int*)g_bitmap4 + b * WPB;
    float* occ = out + X_ELEMS + (long)b * OCC_PER_B;

    int w = c * 32 + lane;
    unsigned int bits = 0;
    if (w < WPB) {
        bits = bm[w];                     // coalesced: one 128B line per warp
        bm[w] = 0;                        // reset for next graph replay
    }

    int nib = (lane & 7) * 4;
    int qbase = c * 256 + lane;           // c*256 <= 4,293,376 < 2^31
    #pragma unroll
    for (int i = 0; i < 8; i++) {
        unsigned int src = __shfl_sync(0xFFFFFFFFu, bits, i * 4 + (lane >> 3));
        int q = qbase + i * 32;
        if (q < Q_PER_B) {
            float4 f;
            f.x = (src >> (nib + 0)) & 1u ? 1.0f : 0.0f;
            f.y = (src >> (nib + 1)) & 1u ? 1.0f : 0.0f;
            f.z = (src >> (nib + 2)) & 1u ? 1.0f : 0.0f;
            f.w = (src >> (nib + 3)) & 1u ? 1.0f : 0.0f;
            *(float4*)(occ + (long)q * 4) = f;
        }
    }
}

extern "C" void kernel_launch(void* const* d_in, const int* in_sizes, int n_in,
                              void* d_out, int out_size) {
    // metadata order:
    // 0 imgs (unused), 1 curves, 2 surfaces, 3 t_line, 4 uv,
    // 5 lines_array, 6 faces_array, 7 indices_array (unused),
    // 8 line_choice, 9 tri_choice
    const float* curves      = (const float*)d_in[1];
    const float* surfaces    = (const float*)d_in[2];
    const float* t_line      = (const float*)d_in[3];
    const float* uv          = (const float*)d_in[4];
    const int*   lines_array = (const int*)d_in[5];
    const int*   faces_array = (const int*)d_in[6];
    const int*   line_choice = (const int*)d_in[8];
    const int*   tri_choice  = (const int*)d_in[9];
    float* out = (float*)d_out;

    // k0: points + bit scatter (bitmap all-zero at entry: zero-init on first
    // call, re-zeroed by the previous sweep on every replay)
    int pb = (NPTOT + 255) / 256;
    points_kernel<<<pb, 256>>>(curves, surfaces, t_line, uv,
                               lines_array, faces_array,
                               line_choice, tri_choice, out);

    // k1: dense 274 MB sweep from bitmap (+ bitmap self-reset)
    // 8 warps per block -> one chunk per warp
    int sb = (NCH * 32 + 255) / 256;      // 8386 blocks
    sweep_kernel<<<sb, 256>>>(out);
}

// round 15
// speedup vs baseline: 2.6760x; 2.0062x over previous
#include <cuda_runtime.h>
#include <cuda_bf16.h>

// Problem constants
#define NB    4
#define NC    2000      // curves per batch
#define NLS   2000      // line samples per batch
#define NS    4000      // surfaces per batch
#define NF    8000      // faces per batch
#define NTS   26000     // triangle samples per batch
#define NPT   (NC + NLS + NS + NTS)   // 34000 points per batch
#define NPTOT (NB * NPT)              // 136000 points total
#define OG    258       // occ grid edge (256 + 2*2 pad - 3 + 1)
#define OGSQ  (OG * OG)                        // 66564
#define X_ELEMS   (NB * NPT * 3)               // 408000
#define OCC_PER_B 17173512L                    // OG^3, divisible by 4
#define OCC_ELEMS (NB * OCC_PER_B)             // 68,669,448

#define N4_PER_B ((int)(OCC_PER_B / 4))        // 4,293,378 float4 per slab
#define ZB       ((N4_PER_B + 255) / 256)      // 16772 zero blocks per slab
#define PTBLK    ((NPTOT + 255) / 256)         // 532 points blocks
#define SCTHREADS (9 * NPT)                    // 306000
#define SCB      ((SCTHREADS + 255) / 256)     // 1196 scatter blocks

// Scratch: packed voxel coords per point (c0 | c1<<8 | c2<<16).
__device__ int g_coords[NPTOT];

__device__ __forceinline__ int cube_coord(float p) {
    float t = __fadd_rn(__fmul_rn(p, 256.0f), 128.5f);
    t = fminf(255.0f, fmaxf(0.0f, t));
    return (int)t;   // t >= 0 so truncation == floor
}

// ---------------------------------------------------------------------------
// points job: one thread per point. Exact f32 op order of the reference
// (no FMA contraction). Writes x and the packed voxel coord.
// ---------------------------------------------------------------------------
__device__ __forceinline__ void points_job(int idx,
                              const float* __restrict__ curves,
                              const float* __restrict__ surfaces,
                              const float* __restrict__ t_line,
                              const float* __restrict__ uv,
                              const int*   __restrict__ lines_array,
                              const int*   __restrict__ faces_array,
                              const int*   __restrict__ line_choice,
                              const int*   __restrict__ tri_choice,
                              float* __restrict__ out) {
    int b = idx / NPT;
    int j = idx - b * NPT;

    float p0, p1, p2;

    if (j < NC) {
        // segment 0: curves passthrough
        const float* c = curves + ((long)(b * NC + j)) * 3;
        p0 = c[0]; p1 = c[1]; p2 = c[2];
    } else if (j < NC + NLS) {
        // segment 1: line interpolation  a + t*(b-a)
        int jj = j - NC;
        int lc = line_choice[b * NLS + jj];
        int s0 = lines_array[((long)(b * NC + lc)) * 2 + 0];
        int s1 = lines_array[((long)(b * NC + lc)) * 2 + 1];
        const float* A  = curves + ((long)(b * NC + s0)) * 3;
        const float* Bp = curves + ((long)(b * NC + s1)) * 3;
        float t = t_line[b * NLS + jj];
        p0 = __fadd_rn(A[0], __fmul_rn(t, __fsub_rn(Bp[0], A[0])));
        p1 = __fadd_rn(A[1], __fmul_rn(t, __fsub_rn(Bp[1], A[1])));
        p2 = __fadd_rn(A[2], __fmul_rn(t, __fsub_rn(Bp[2], A[2])));
    } else if (j < NC + NLS + NS) {
        // segment 2: surfaces passthrough
        int jj = j - (NC + NLS);
        const float* s = surfaces + ((long)(b * NS + jj)) * 3;
        p0 = s[0]; p1 = s[1]; p2 = s[2];
    } else {
        // segment 3: triangle barycentric sample
        int jj = j - (NC + NLS + NS);
        int tc = tri_choice[b * NTS + jj];
        const int* f = faces_array + ((long)(b * NF + tc)) * 3;
        const float* ta  = surfaces + ((long)(b * NS + f[0])) * 3;
        const float* tb  = surfaces + ((long)(b * NS + f[1])) * 3;
        const float* tcx = surfaces + ((long)(b * NS + f[2])) * 3;
        float u = uv[((long)(b * NTS + jj)) * 2 + 0];
        float v = uv[((long)(b * NTS + jj)) * 2 + 1];
        if (__fadd_rn(u, v) > 1.0f) {
            u = __fsub_rn(1.0f, u);
            v = __fsub_rn(1.0f, v);
        }
        // (ta + u*(tb-ta)) + v*(tc-ta), exact reference op order
        p0 = __fadd_rn(__fadd_rn(ta[0], __fmul_rn(u, __fsub_rn(tb[0], ta[0]))),
                       __fmul_rn(v, __fsub_rn(tcx[0], ta[0])));
        p1 = __fadd_rn(__fadd_rn(ta[1], __fmul_rn(u, __fsub_rn(tb[1], ta[1]))),
                       __fmul_rn(v, __fsub_rn(tcx[1], ta[1])));
        p2 = __fadd_rn(__fadd_rn(ta[2], __fmul_rn(u, __fsub_rn(tb[2], ta[2]))),
                       __fmul_rn(v, __fsub_rn(tcx[2], ta[2])));
    }

    float* xo = out + ((long)idx) * 3;
    xo[0] = p0; xo[1] = p1; xo[2] = p2;

    int c0 = cube_coord(p0);
    int c1 = cube_coord(p1);
    int c2 = cube_coord(p2);
    g_coords[idx] = c0 | (c1 << 8) | (c2 << 16);
}

// ---------------------------------------------------------------------------
// Kernel A (launch 0): points blocks [0, PTBLK) + one-shot zero of slab 0
// in blocks [PTBLK, PTBLK+ZB). Disjoint address sets (x+coords vs occ slab
// 0); points' few-MB traffic is too small to disturb the streaming sweep.
// ---------------------------------------------------------------------------
__global__ void points_zero0_kernel(float* __restrict__ out,
                             const float* __restrict__ curves,
                             const float* __restrict__ surfaces,
                             const float* __restrict__ t_line,
                             const float* __restrict__ uv,
                             const int*   __restrict__ lines_array,
                             const int*   __restrict__ faces_array,
                             const int*   __restrict__ line_choice,
                             const int*   __restrict__ tri_choice) {
    if ((int)blockIdx.x < PTBLK) {
        int idx = blockIdx.x * blockDim.x + threadIdx.x;
        if (idx < NPTOT)
            points_job(idx, curves, surfaces, t_line, uv,
                       lines_array, faces_array, line_choice, tri_choice, out);
        return;
    }
    // zero slab 0 (one float4 per thread, same structure as the proven
    // 5.6+ TB/s per-batch zero)
    int i = ((int)blockIdx.x - PTBLK) * blockDim.x + threadIdx.x;
    if (i < N4_PER_B)
        ((float4*)(out + X_ELEMS))[i] = make_float4(0.f, 0.f, 0.f, 0.f);
}

// ---------------------------------------------------------------------------
// Zero kernel: one-shot float4 zero of slab b (identical to R10 champion).
// ---------------------------------------------------------------------------
__global__ void zero_batch_kernel(float4* __restrict__ p) {
    int i = blockIdx.x * blockDim.x + threadIdx.x;
    if (i < N4_PER_B) p[i] = make_float4(0.f, 0.f, 0.f, 0.f);
}

// ---------------------------------------------------------------------------
// Scatter kernel for one batch: one thread per (point, d0, d1) writes one
// 3-float row of the dilated 3x3x3 block. Runs immediately after that
// slab's zero -> touched lines are L2-resident (dirty): stores are L2
// partial-sector hits, no DRAM read-modify-write. Dilation == padded
// 3-maxpool of the one-hot grid; coords always in-bounds; writes idempotent
// 1.0f -> no races.
// ---------------------------------------------------------------------------
__global__ void scatter_batch_kernel(float* __restrict__ occ, int b) {
    int t = blockIdx.x * blockDim.x + threadIdx.x;
    if (t >= SCTHREADS) return;
    int r = t / NPT;                 // 0..8
    int pidx = t - r * NPT;
    int d0 = r / 3;
    int d1 = r - d0 * 3;

    int packed = g_coords[b * NPT + pidx];     // coalesced; L2-hit across r
    int c0 = packed & 0xFF;
    int c1 = (packed >> 8) & 0xFF;
    int c2 = (packed >> 16) & 0xFF;

    float* row = occ + (long)(c0 + d0) * OGSQ + (long)(c1 + d1) * OG + c2;
    row[0] = 1.0f; row[1] = 1.0f; row[2] = 1.0f;
}

extern "C" void kernel_launch(void* const* d_in, const int* in_sizes, int n_in,
                              void* d_out, int out_size) {
    // metadata order:
    // 0 imgs (unused), 1 curves, 2 surfaces, 3 t_line, 4 uv,
    // 5 lines_array, 6 faces_array, 7 indices_array (unused),
    // 8 line_choice, 9 tri_choice
    const float* curves      = (const float*)d_in[1];
    const float* surfaces    = (const float*)d_in[2];
    const float* t_line      = (const float*)d_in[3];
    const float* uv          = (const float*)d_in[4];
    const int*   lines_array = (const int*)d_in[5];
    const int*   faces_array = (const int*)d_in[6];
    const int*   line_choice = (const int*)d_in[8];
    const int*   tri_choice  = (const int*)d_in[9];
    float* out = (float*)d_out;

    // k0: points || zero slab 0
    points_zero0_kernel<<<PTBLK + ZB, 256>>>(out, curves, surfaces, t_line,
                                             uv, lines_array, faces_array,
                                             line_choice, tri_choice);
    // scatter slab 0 (slab 0 L2-resident from k0)
    scatter_batch_kernel<<<SCB, 256>>>(out + X_ELEMS, 0);

    // slabs 1..3: zero then scatter (R10 champion choreography)
    for (int b = 1; b < NB; b++) {
        float* occ_b = out + X_ELEMS + (long)b * OCC_PER_B;
        zero_batch_kernel<<<ZB, 256>>>((float4*)occ_b);
        scatter_batch_kernel<<<SCB, 256>>>(occ_b, b);
    }
}